// round 4
// baseline (speedup 1.0000x reference)
#include <cuda_runtime.h>
#include <math.h>

// Problem constants
#define HDIM   4096
#define HDIM4  1024          // HDIM / 4
#define MSTK   104
#define NB     512           // GEMV blocks: 8 rows/block, 1 row per warp

// Inter-kernel scratch for h (no allocation allowed; static device array)
__device__ float g_h[HDIM];

// ---------------------------------------------------------------------------
// Kernel 1: h = tanh(W_ih @ emb + b_ih + W_hh @ hbar + b_hh)
//   emb  = E[inp[0]]
//   hbar = W_sh[:,0]*stack[0] + b_sh + hidden0
// Grid: 512 blocks x 256 threads. One warp per row, 2 weight streams per warp.
// First 8 float4 of each weight stream are prefetched BEFORE the barrier.
// ---------------------------------------------------------------------------
__global__ __launch_bounds__(256, 4)
void k_hidden(const int* __restrict__ inp,
              const float* __restrict__ hidden0,
              const float* __restrict__ stack,
              const float* __restrict__ E,
              const float* __restrict__ W_ih,
              const float* __restrict__ b_ih,
              const float* __restrict__ W_hh,
              const float* __restrict__ b_hh,
              const float* __restrict__ W_sh,
              const float* __restrict__ b_sh,
              float* __restrict__ out_hidden)   // d_out + 4096
{
    __shared__ float s_emb[HDIM];
    __shared__ float s_hbar[HDIM];

    const int tid  = threadIdx.x;
    const int warp = tid >> 5;
    const int lane = tid & 31;
    const int row  = blockIdx.x * 8 + warp;

    const float4* __restrict__ wi = (const float4*)(W_ih + (size_t)row * HDIM);
    const float4* __restrict__ wh = (const float4*)(W_hh + (size_t)row * HDIM);

    // Software prefetch: first 4 chunks of each weight stream, issued before
    // the shared-memory preamble so DRAM latency overlaps the barrier.
    float4 pa[4], pb[4];
    #pragma unroll
    for (int j = 0; j < 4; j++) {
        pa[j] = __ldcs(&wi[lane + 32 * j]);
        pb[j] = __ldcs(&wh[lane + 32 * j]);
    }

    const int erow = inp[0];
    const float s0 = stack[0];

    const float4* __restrict__ E4   = (const float4*)(E + (size_t)erow * HDIM);
    const float4* __restrict__ Wsh4 = (const float4*)W_sh;
    const float4* __restrict__ bsh4 = (const float4*)b_sh;
    const float4* __restrict__ h04  = (const float4*)hidden0;

    #pragma unroll
    for (int i = tid; i < HDIM4; i += 256) {
        ((float4*)s_emb)[i] = E4[i];
        float4 ws = Wsh4[i];
        float4 bs = bsh4[i];
        float4 h0 = h04[i];
        float4 hb;
        hb.x = fmaf(ws.x, s0, bs.x) + h0.x;
        hb.y = fmaf(ws.y, s0, bs.y) + h0.y;
        hb.z = fmaf(ws.z, s0, bs.z) + h0.z;
        hb.w = fmaf(ws.w, s0, bs.w) + h0.w;
        ((float4*)s_hbar)[i] = hb;
    }
    __syncthreads();

    const float4* __restrict__ se4 = (const float4*)s_emb;
    const float4* __restrict__ sh4 = (const float4*)s_hbar;

    float ai0 = 0.f, ai1 = 0.f, ai2 = 0.f, ai3 = 0.f;
    float ah0 = 0.f, ah1 = 0.f, ah2 = 0.f, ah3 = 0.f;

    // Consume the prefetched chunks
    #pragma unroll
    for (int j = 0; j < 4; j++) {
        const int k = lane + 32 * j;
        float4 a  = pa[j];
        float4 b  = pb[j];
        float4 e  = se4[k];
        float4 hb = sh4[k];
        switch (j) {
        case 0:
            ai0 = fmaf(a.x, e.x,  fmaf(a.y, e.y,  fmaf(a.z, e.z,  fmaf(a.w, e.w,  ai0))));
            ah0 = fmaf(b.x, hb.x, fmaf(b.y, hb.y, fmaf(b.z, hb.z, fmaf(b.w, hb.w, ah0))));
            break;
        case 1:
            ai1 = fmaf(a.x, e.x,  fmaf(a.y, e.y,  fmaf(a.z, e.z,  fmaf(a.w, e.w,  ai1))));
            ah1 = fmaf(b.x, hb.x, fmaf(b.y, hb.y, fmaf(b.z, hb.z, fmaf(b.w, hb.w, ah1))));
            break;
        case 2:
            ai2 = fmaf(a.x, e.x,  fmaf(a.y, e.y,  fmaf(a.z, e.z,  fmaf(a.w, e.w,  ai2))));
            ah2 = fmaf(b.x, hb.x, fmaf(b.y, hb.y, fmaf(b.z, hb.z, fmaf(b.w, hb.w, ah2))));
            break;
        default:
            ai3 = fmaf(a.x, e.x,  fmaf(a.y, e.y,  fmaf(a.z, e.z,  fmaf(a.w, e.w,  ai3))));
            ah3 = fmaf(b.x, hb.x, fmaf(b.y, hb.y, fmaf(b.z, hb.z, fmaf(b.w, hb.w, ah3))));
            break;
        }
    }

    // Remaining 28 chunks, fully unrolled for deep MLP
    #pragma unroll
    for (int j = 4; j < 32; j++) {
        const int k = lane + 32 * j;
        float4 a  = __ldcs(&wi[k]);
        float4 b  = __ldcs(&wh[k]);
        float4 e  = se4[k];
        float4 hb = sh4[k];
        switch (j & 3) {
        case 0:
            ai0 = fmaf(a.x, e.x,  fmaf(a.y, e.y,  fmaf(a.z, e.z,  fmaf(a.w, e.w,  ai0))));
            ah0 = fmaf(b.x, hb.x, fmaf(b.y, hb.y, fmaf(b.z, hb.z, fmaf(b.w, hb.w, ah0))));
            break;
        case 1:
            ai1 = fmaf(a.x, e.x,  fmaf(a.y, e.y,  fmaf(a.z, e.z,  fmaf(a.w, e.w,  ai1))));
            ah1 = fmaf(b.x, hb.x, fmaf(b.y, hb.y, fmaf(b.z, hb.z, fmaf(b.w, hb.w, ah1))));
            break;
        case 2:
            ai2 = fmaf(a.x, e.x,  fmaf(a.y, e.y,  fmaf(a.z, e.z,  fmaf(a.w, e.w,  ai2))));
            ah2 = fmaf(b.x, hb.x, fmaf(b.y, hb.y, fmaf(b.z, hb.z, fmaf(b.w, hb.w, ah2))));
            break;
        default:
            ai3 = fmaf(a.x, e.x,  fmaf(a.y, e.y,  fmaf(a.z, e.z,  fmaf(a.w, e.w,  ai3))));
            ah3 = fmaf(b.x, hb.x, fmaf(b.y, hb.y, fmaf(b.z, hb.z, fmaf(b.w, hb.w, ah3))));
            break;
        }
    }

    float acc = (ai0 + ai1) + (ai2 + ai3) + (ah0 + ah1) + (ah2 + ah3);
    #pragma unroll
    for (int o = 16; o > 0; o >>= 1)
        acc += __shfl_down_sync(0xFFFFFFFFu, acc, o);

    if (lane == 0) {
        float hv = tanhf(acc + b_ih[row] + b_hh[row]);
        g_h[row] = hv;
        out_hidden[row] = hv;
    }
}

// ---------------------------------------------------------------------------
// Kernel 2:
//   blocks 0..NB-1 : output = sigmoid(W_y @ h + b_y)        -> out[0:4096]
//   block NB       : softmax head + new_elt + stack blend + weights
// ---------------------------------------------------------------------------
__global__ __launch_bounds__(256, 4)
void k_out(const float* __restrict__ W_y,
           const float* __restrict__ b_y,
           const float* __restrict__ W_n,
           const float* __restrict__ b_n,
           const float* __restrict__ W_a,
           const float* __restrict__ b_a,
           const float* __restrict__ stack,
           float* __restrict__ out)
{
    __shared__ float s_h[HDIM];
    __shared__ float red[3][8];
    __shared__ float s_small[3];   // aw0, aw1, new_elt

    const int tid  = threadIdx.x;
    const int warp = tid >> 5;
    const int lane = tid & 31;

    if (blockIdx.x < NB) {
        const int row = blockIdx.x * 8 + warp;
        const float4* __restrict__ wy = (const float4*)(W_y + (size_t)row * HDIM);

        // Prefetch first 4 weight chunks before the s_h preamble/barrier
        float4 pa[4];
        #pragma unroll
        for (int j = 0; j < 4; j++) pa[j] = __ldcs(&wy[lane + 32 * j]);

        #pragma unroll
        for (int i = tid; i < HDIM; i += 256) s_h[i] = g_h[i];
        __syncthreads();

        const float4* __restrict__ sh4 = (const float4*)s_h;

        float a0 = 0.f, a1 = 0.f, a2 = 0.f, a3 = 0.f;
        #pragma unroll
        for (int j = 0; j < 4; j++) {
            const int k = lane + 32 * j;
            float4 a  = pa[j];
            float4 h4 = sh4[k];
            switch (j) {
            case 0:  a0 = fmaf(a.x, h4.x, fmaf(a.y, h4.y, fmaf(a.z, h4.z, fmaf(a.w, h4.w, a0)))); break;
            case 1:  a1 = fmaf(a.x, h4.x, fmaf(a.y, h4.y, fmaf(a.z, h4.z, fmaf(a.w, h4.w, a1)))); break;
            case 2:  a2 = fmaf(a.x, h4.x, fmaf(a.y, h4.y, fmaf(a.z, h4.z, fmaf(a.w, h4.w, a2)))); break;
            default: a3 = fmaf(a.x, h4.x, fmaf(a.y, h4.y, fmaf(a.z, h4.z, fmaf(a.w, h4.w, a3)))); break;
            }
        }
        #pragma unroll
        for (int j = 4; j < 32; j++) {
            const int k = lane + 32 * j;
            float4 a  = __ldcs(&wy[k]);
            float4 h4 = sh4[k];
            switch (j & 3) {
            case 0:  a0 = fmaf(a.x, h4.x, fmaf(a.y, h4.y, fmaf(a.z, h4.z, fmaf(a.w, h4.w, a0)))); break;
            case 1:  a1 = fmaf(a.x, h4.x, fmaf(a.y, h4.y, fmaf(a.z, h4.z, fmaf(a.w, h4.w, a1)))); break;
            case 2:  a2 = fmaf(a.x, h4.x, fmaf(a.y, h4.y, fmaf(a.z, h4.z, fmaf(a.w, h4.w, a2)))); break;
            default: a3 = fmaf(a.x, h4.x, fmaf(a.y, h4.y, fmaf(a.z, h4.z, fmaf(a.w, h4.w, a3)))); break;
            }
        }
        float acc = (a0 + a1) + (a2 + a3);
        #pragma unroll
        for (int o = 16; o > 0; o >>= 1)
            acc += __shfl_down_sync(0xFFFFFFFFu, acc, o);
        if (lane == 0) {
            float z = acc + b_y[row];
            out[row] = 1.0f / (1.0f + expf(-z));   // sigmoid
        }
    } else {
        // --- small block: W_a (2xH), W_n (1xH), softmax, stack blend ---
        #pragma unroll
        for (int i = tid; i < HDIM; i += 256) s_h[i] = g_h[i];
        __syncthreads();

        float p0 = 0.0f, p1 = 0.0f, pn = 0.0f;
        for (int i = tid; i < HDIM; i += 256) {
            float hv = s_h[i];
            p0 = fmaf(W_a[i],        hv, p0);
            p1 = fmaf(W_a[HDIM + i], hv, p1);
            pn = fmaf(W_n[i],        hv, pn);
        }
        #pragma unroll
        for (int o = 16; o > 0; o >>= 1) {
            p0 += __shfl_down_sync(0xFFFFFFFFu, p0, o);
            p1 += __shfl_down_sync(0xFFFFFFFFu, p1, o);
            pn += __shfl_down_sync(0xFFFFFFFFu, pn, o);
        }
        if (lane == 0) { red[0][warp] = p0; red[1][warp] = p1; red[2][warp] = pn; }
        __syncthreads();
        if (tid == 0) {
            float z0 = b_a[0], z1 = b_a[1], zn = b_n[0];
            #pragma unroll
            for (int w = 0; w < 8; w++) { z0 += red[0][w]; z1 += red[1][w]; zn += red[2][w]; }
            float m  = fmaxf(z0, z1);
            float e0 = expf(z0 - m);
            float e1 = expf(z1 - m);
            float inv = 1.0f / (e0 + e1);
            float aw0 = e0 * inv;
            float aw1 = e1 * inv;
            s_small[0] = aw0;
            s_small[1] = aw1;
            s_small[2] = 1.0f / (1.0f + expf(-zn));    // new_elt
            out[8296] = aw0 + aw1;                      // weights
        }
        __syncthreads();
        const float aw0 = s_small[0];
        const float aw1 = s_small[1];
        const float ne  = s_small[2];
        if (tid < MSTK) {
            float push = (tid == 0)       ? ne : stack[tid - 1];
            float pop  = (tid < MSTK - 1) ? stack[tid + 1] : 0.0f;
            out[8192 + tid] = fmaf(aw0, push, aw1 * pop);
        }
    }
}

// ---------------------------------------------------------------------------
// kernel_launch
// Inputs: 0 inp(i32), 1 hidden0, 2 stack, 3 E, 4 W_ih, 5 b_ih, 6 W_hh, 7 b_hh,
//   8 W_y, 9 b_y, 10 W_n, 11 b_n, 12 W_a, 13 b_a, 14 W_sh, 15 b_sh
// Output (fp32, 8297): [0:4096) output, [4096:8192) hidden,
//   [8192:8296) new_stack, [8296] weights
// ---------------------------------------------------------------------------
extern "C" void kernel_launch(void* const* d_in, const int* in_sizes, int n_in,
                              void* d_out, int out_size)
{
    const int*   inp     = (const int*)  d_in[0];
    const float* hidden0 = (const float*)d_in[1];
    const float* stack   = (const float*)d_in[2];
    const float* E       = (const float*)d_in[3];
    const float* W_ih    = (const float*)d_in[4];
    const float* b_ih    = (const float*)d_in[5];
    const float* W_hh    = (const float*)d_in[6];
    const float* b_hh    = (const float*)d_in[7];
    const float* W_y     = (const float*)d_in[8];
    const float* b_y     = (const float*)d_in[9];
    const float* W_n     = (const float*)d_in[10];
    const float* b_n     = (const float*)d_in[11];
    const float* W_a     = (const float*)d_in[12];
    const float* b_a     = (const float*)d_in[13];
    const float* W_sh    = (const float*)d_in[14];
    const float* b_sh    = (const float*)d_in[15];

    float* out = (float*)d_out;

    k_hidden<<<NB, 256>>>(inp, hidden0, stack, E, W_ih, b_ih, W_hh, b_hh,
                          W_sh, b_sh, out + 4096);
    k_out<<<NB + 1, 256>>>(W_y, b_y, W_n, b_n, W_a, b_a, stack, out);
}